// round 17
// baseline (speedup 1.0000x reference)
#include <cuda_runtime.h>
#include <cuda_fp16.h>
#include <cstdint>

#define NSEQ   8192
#define DH     64
#define BR     128
#define BC     64
#define NT     128
#define NHALF  64                 // KV tiles per half (split-KV factor 2)
#define LOG2E  1.4426950408889634f

// ---- smem (bytes) ----
// main: 2 stages x (Kh [64][72h] + Vh [64][72h]); stride 144B (16 mod 128)
// main epilogue: Os [128][68] raw-O staging (34816B) aliases stages
#define KH_BYTES (64 * 144)
#define VH_BYTES (64 * 144)
#define STG_BYTES (KH_BYTES + VH_BYTES)          // 18432
#define KH_OFF(s) ((s) * STG_BYTES)
#define VH_OFF(s) (KH_OFF(s) + KH_BYTES)
#define OSTR      68                             // floats; 68%4==0 -> f4-aligned rows
#define OS_BYTES  (BR * OSTR * 4)                // 34816
#define SMEM_MAIN (2 * STG_BYTES)                // 36864 (>= OS_BYTES)
#define SMEM_COMB (OS_BYTES + DH * DH * 4)       // 51200

#define ONES_H2  0x3C003C00u                     // half2(1.0, 1.0)

typedef unsigned long long u64;

__device__ __half g_xh [4 * DH * NSEQ];   // [b][f][n]  4MB
__device__ __half g_xhT[4 * NSEQ * DH];   // [b][n][f]  4MB
__device__ float  g_rq2[4][NSEQ];         // ||q||^2 (fp16-quantized q)
__device__ float  g_Opart[2][4][NSEQ * DH];  // unnormalized O halves, 16MB
__device__ float  g_lpart[2][4][NSEQ];       // l halves

// ---------------- helpers ----------------
__device__ __forceinline__ uint32_t smem_u32(const void* p) {
    uint32_t a;
    asm("{ .reg .u64 t; cvta.to.shared.u64 t, %1; cvt.u32.u64 %0, t; }" : "=r"(a) : "l"(p));
    return a;
}
__device__ __forceinline__ void mma16(float* d, uint32_t a0, uint32_t a1, uint32_t a2,
                                      uint32_t a3, uint32_t b0, uint32_t b1) {
    asm volatile("mma.sync.aligned.m16n8k16.row.col.f32.f16.f16.f32 "
        "{%0,%1,%2,%3}, {%4,%5,%6,%7}, {%8,%9}, {%0,%1,%2,%3};"
        : "+f"(d[0]), "+f"(d[1]), "+f"(d[2]), "+f"(d[3])
        : "r"(a0), "r"(a1), "r"(a2), "r"(a3), "r"(b0), "r"(b1));
}
__device__ __forceinline__ void ldsm4(uint32_t* r, uint32_t addr) {
    asm volatile("ldmatrix.sync.aligned.m8n8.x4.shared.b16 {%0,%1,%2,%3}, [%4];"
        : "=r"(r[0]), "=r"(r[1]), "=r"(r[2]), "=r"(r[3]) : "r"(addr));
}
__device__ __forceinline__ uint32_t exp2h2(float f0, float f1) {
    uint32_t h, r;
    asm("cvt.rn.f16x2.f32 %0, %1, %2;" : "=r"(h) : "f"(f1), "f"(f0));
    asm("ex2.approx.f16x2 %0, %1;" : "=r"(r) : "r"(h));
    return r;
}
__device__ __forceinline__ void cpasync16(uint32_t dst, const void* src) {
    asm volatile("cp.async.ca.shared.global [%0], [%1], 16;" :: "r"(dst), "l"(src));
}
#define CP_COMMIT()  asm volatile("cp.async.commit_group;" ::: "memory")
#define CP_WAIT(n)   asm volatile("cp.async.wait_group %0;" :: "n"(n) : "memory")

__device__ __forceinline__ u64 dup2f(float x) {
    u64 r; asm("mov.b64 %0, {%1, %1};" : "=l"(r) : "f"(x)); return r;
}
__device__ __forceinline__ void unpack2f(u64 v, float& lo, float& hi) {
    asm("mov.b64 {%0, %1}, %2;" : "=f"(lo), "=f"(hi) : "l"(v));
}
__device__ __forceinline__ void fma2(u64& d, u64 a, u64 b) {
    asm("fma.rn.f32x2 %0, %1, %2, %0;" : "+l"(d) : "l"(a), "l"(b));
}
__device__ __forceinline__ u64 mul2(u64 a, u64 b) {
    u64 r; asm("mul.rn.f32x2 %0, %1, %2;" : "=l"(r) : "l"(a), "l"(b)); return r;
}

// ---- pre-pass: fp16-quantize x into both layouts + per-row squared norms ----
__global__ void prep_kernel(const float* __restrict__ x) {
    int b = blockIdx.y;
    int n = blockIdx.x * 256 + threadIdx.x;
    const float* xb = x + b * DH * NSEQ;
    __half* xh  = g_xh  + b * DH * NSEQ;
    __half* xhT = g_xhT + b * NSEQ * DH;
    float s = 0.0f;
    #pragma unroll
    for (int f = 0; f < DH; ++f) {
        float v = xb[f * NSEQ + n];
        __half h = __float2half_rn(v);
        float vq = __half2float(h);
        xh[f * NSEQ + n]  = h;
        xhT[n * DH + f]   = h;
        s = fmaf(vq, vq, s);
    }
    g_rq2[b][n] = s;
}

// ---------------- main kernel: one KV half per CTA, raw O/l partials out ----
// 4 warps x 32 rows, R16 jp-pipeline (low live regs), 3 CTAs/SM target.
__global__ void __launch_bounds__(NT, 3) fa_h16_kernel() {
    extern __shared__ char smem[];
    const uint32_t sb = smem_u32(smem);

    const int t   = threadIdx.x;
    const int wp  = t >> 5;
    const int l   = t & 31;
    const int g   = l >> 2;
    const int tig = l & 3;
    const int b    = blockIdx.y;
    const int z    = blockIdx.z;           // KV half
    const int row0 = blockIdx.x * BR;
    const int m00  = z * NHALF * BC;       // KV base offset for this half
    const __half* xh  = g_xh  + b * DH * NSEQ;
    const __half* xhT = g_xhT + b * NSEQ * DH;

    const uint32_t lmoff = (uint32_t)((8 * ((l >> 3) >> 1) + (l & 7)) * 144
                                      + ((l >> 3) & 1) * 16);

    // Q fp16 A-frags pinned in registers
    uint32_t aq[2][4][4];
    #pragma unroll
    for (int mi = 0; mi < 2; ++mi) {
        const int i0 = row0 + wp * 32 + mi * 16 + g;
        #pragma unroll
        for (int kt = 0; kt < 4; ++kt) {
            aq[mi][kt][0] = *(const uint32_t*)(xhT + (size_t)i0 * DH + 16 * kt + 2 * tig);
            aq[mi][kt][1] = *(const uint32_t*)(xhT + (size_t)(i0 + 8) * DH + 16 * kt + 2 * tig);
            aq[mi][kt][2] = *(const uint32_t*)(xhT + (size_t)i0 * DH + 16 * kt + 2 * tig + 8);
            aq[mi][kt][3] = *(const uint32_t*)(xhT + (size_t)(i0 + 8) * DH + 16 * kt + 2 * tig + 8);
        }
    }

    const uint32_t onesb = (g == 0) ? ONES_H2 : 0u;

    float m2n[2][2];
    #pragma unroll
    for (int mi = 0; mi < 2; ++mi) {
        int r1 = row0 + wp * 32 + mi * 16 + g;
        m2n[mi][0] = -g_rq2[b][r1]     * LOG2E;
        m2n[mi][1] = -g_rq2[b][r1 + 8] * LOG2E;
    }

    float Oa[2][8][4], Ol[2][4];
    #pragma unroll
    for (int mi = 0; mi < 2; ++mi) {
        #pragma unroll
        for (int j = 0; j < 8; ++j)
            #pragma unroll
            for (int r = 0; r < 4; ++r) Oa[mi][j][r] = 0.0f;
        #pragma unroll
        for (int r = 0; r < 4; ++r) Ol[mi][r] = 0.0f;
    }

    // prologue: tile 0 of this half -> buf 0
    #pragma unroll
    for (int k = 0; k < 4; ++k) {
        int ci = k * NT + t, r = ci >> 3, c = ci & 7;
        cpasync16(sb + KH_OFF(0) + r * 144 + c * 16, xhT + (size_t)(m00 + r) * DH + c * 8);
        cpasync16(sb + VH_OFF(0) + r * 144 + c * 16, xh + (size_t)r * NSEQ + m00 + c * 8);
    }
    CP_COMMIT();
    __syncthreads();

    for (int ct = 0; ct < NHALF; ++ct) {
        const int buf = ct & 1;
        {
            const int mn = m00 + ((ct + 1) & (NHALF - 1)) * BC;
            #pragma unroll
            for (int k = 0; k < 4; ++k) {
                int ci = k * NT + t, r = ci >> 3, c = ci & 7;
                cpasync16(sb + KH_OFF(buf ^ 1) + r * 144 + c * 16,
                          xhT + (size_t)(mn + r) * DH + c * 8);
                cpasync16(sb + VH_OFF(buf ^ 1) + r * 144 + c * 16,
                          xh + (size_t)r * NSEQ + mn + c * 8);
            }
            CP_COMMIT();
        }
        CP_WAIT(1);
        __syncthreads();

        const uint32_t kbase = sb + KH_OFF(buf) + lmoff;
        const uint32_t vbase = sb + VH_OFF(buf) + lmoff;

        float Sa[2][2][4];
        uint32_t phc[2][2][2][2];

        #define S_BLOCK(jp_) {                                                    \
            _Pragma("unroll")                                                     \
            for (int mi = 0; mi < 2; ++mi)                                        \
                _Pragma("unroll")                                                 \
                for (int js = 0; js < 2; ++js)                                    \
                    _Pragma("unroll")                                             \
                    for (int r = 0; r < 4; ++r) Sa[mi][js][r] = 0.0f;             \
            _Pragma("unroll")                                                     \
            for (int kt = 0; kt < 4; ++kt) {                                      \
                uint32_t bk[4];                                                   \
                ldsm4(bk, kbase + (jp_) * 2304 + kt * 32);                        \
                mma16(Sa[0][0], aq[0][kt][0], aq[0][kt][1], aq[0][kt][2],         \
                      aq[0][kt][3], bk[0], bk[1]);                                \
                mma16(Sa[1][0], aq[1][kt][0], aq[1][kt][1], aq[1][kt][2],         \
                      aq[1][kt][3], bk[0], bk[1]);                                \
                mma16(Sa[0][1], aq[0][kt][0], aq[0][kt][1], aq[0][kt][2],         \
                      aq[0][kt][3], bk[2], bk[3]);                                \
                mma16(Sa[1][1], aq[1][kt][0], aq[1][kt][1], aq[1][kt][2],         \
                      aq[1][kt][3], bk[2], bk[3]);                                \
            }                                                                     \
        }
        #define SMAX_TO(p_) {                                                     \
            _Pragma("unroll")                                                     \
            for (int mi = 0; mi < 2; ++mi)                                        \
                _Pragma("unroll")                                                 \
                for (int js = 0; js < 2; ++js) {                                  \
                    float f0 = fmaf(Sa[mi][js][0], LOG2E, m2n[mi][0]);            \
                    float f1 = fmaf(Sa[mi][js][1], LOG2E, m2n[mi][0]);            \
                    float f2 = fmaf(Sa[mi][js][2], LOG2E, m2n[mi][1]);            \
                    float f3 = fmaf(Sa[mi][js][3], LOG2E, m2n[mi][1]);            \
                    phc[p_][mi][js][0] = exp2h2(f0, f1);                          \
                    phc[p_][mi][js][1] = exp2h2(f2, f3);                          \
                }                                                                 \
        }
        #define O_BATCH(kt_, p_) {                                                \
            _Pragma("unroll")                                                     \
            for (int jp2 = 0; jp2 < 4; ++jp2) {                                   \
                uint32_t bv[4];                                                   \
                ldsm4(bv, vbase + jp2 * 2304 + (kt_) * 32);                       \
                mma16(Oa[0][2 * jp2],     phc[p_][0][0][0], phc[p_][0][0][1],     \
                      phc[p_][0][1][0], phc[p_][0][1][1], bv[0], bv[1]);          \
                mma16(Oa[1][2 * jp2],     phc[p_][1][0][0], phc[p_][1][0][1],     \
                      phc[p_][1][1][0], phc[p_][1][1][1], bv[0], bv[1]);          \
                mma16(Oa[0][2 * jp2 + 1], phc[p_][0][0][0], phc[p_][0][0][1],     \
                      phc[p_][0][1][0], phc[p_][0][1][1], bv[2], bv[3]);          \
                mma16(Oa[1][2 * jp2 + 1], phc[p_][1][0][0], phc[p_][1][0][1],     \
                      phc[p_][1][1][0], phc[p_][1][1][1], bv[2], bv[3]);          \
            }                                                                     \
            mma16(Ol[0], phc[p_][0][0][0], phc[p_][0][0][1], phc[p_][0][1][0],    \
                  phc[p_][0][1][1], onesb, onesb);                                \
            mma16(Ol[1], phc[p_][1][0][0], phc[p_][1][0][1], phc[p_][1][1][0],    \
                  phc[p_][1][1][1], onesb, onesb);                                \
        }

        S_BLOCK(0)  SMAX_TO(0)
        S_BLOCK(1)  O_BATCH(0, 0)  SMAX_TO(1)
        S_BLOCK(2)  O_BATCH(1, 1)  SMAX_TO(0)
        S_BLOCK(3)  O_BATCH(2, 0)  SMAX_TO(1)
        O_BATCH(3, 1)

        #undef S_BLOCK
        #undef SMAX_TO
        #undef O_BATCH
        __syncthreads();
    }

    CP_WAIT(0);
    __syncthreads();

    // ---- write raw partials: l (ones column lives in c0/c2 of tig==0 lanes) ----
    #pragma unroll
    for (int mi = 0; mi < 2; ++mi) {
        int r1 = wp * 32 + mi * 16 + g;
        if (tig == 0) {
            g_lpart[z][b][row0 + r1]     = Ol[mi][0];
            g_lpart[z][b][row0 + r1 + 8] = Ol[mi][2];
        }
    }
    // raw O frags -> Os staging -> coalesced dump to g_Opart
    float* Os = (float*)smem;
    #pragma unroll
    for (int mi = 0; mi < 2; ++mi) {
        int r1 = wp * 32 + mi * 16 + g;
        #pragma unroll
        for (int j = 0; j < 8; ++j) {
            *(float2*)(Os + r1 * OSTR + 8 * j + 2 * tig) =
                make_float2(Oa[mi][j][0], Oa[mi][j][1]);
            *(float2*)(Os + (r1 + 8) * OSTR + 8 * j + 2 * tig) =
                make_float2(Oa[mi][j][2], Oa[mi][j][3]);
        }
    }
    __syncthreads();
    float* op = &g_Opart[z][b][(size_t)row0 * DH];
    #pragma unroll
    for (int k = 0; k < 16; ++k) {
        int idx = k * NT + t, r = idx >> 4, c4 = idx & 15;
        float4 v = *(const float4*)(Os + r * OSTR + c4 * 4);
        *(float4*)(op + r * DH + c4 * 4) = v;
    }
}

// ---------------- combine: sum halves, normalize, apply W, store transposed ----
__global__ void __launch_bounds__(NT) combine_kernel(const float* __restrict__ w,
                                                     float* __restrict__ out) {
    extern __shared__ char smem[];
    float* Os = (float*)smem;
    float* Ws = (float*)(smem + OS_BYTES);
    const int t = threadIdx.x;
    const int b = blockIdx.y;
    const int row0 = blockIdx.x * BR;

    const float* o0 = &g_Opart[0][b][(size_t)row0 * DH];
    const float* o1 = &g_Opart[1][b][(size_t)row0 * DH];
    #pragma unroll
    for (int k = 0; k < 16; ++k) {
        int idx = k * NT + t, r = idx >> 4, c4 = idx & 15;
        float4 v0 = *(const float4*)(o0 + r * DH + c4 * 4);
        float4 v1 = *(const float4*)(o1 + r * DH + c4 * 4);
        v0.x += v1.x; v0.y += v1.y; v0.z += v1.z; v0.w += v1.w;
        *(float4*)(Os + r * OSTR + c4 * 4) = v0;
    }
    #pragma unroll
    for (int k = 0; k < (DH * DH) / NT; ++k) Ws[k * NT + t] = w[k * NT + t];
    const float inv = 1.0f / (g_lpart[0][b][row0 + t] + g_lpart[1][b][row0 + t]);
    __syncthreads();

    u64 acc[32];
    #pragma unroll
    for (int i = 0; i < 32; ++i) acc[i] = 0ull;
    #pragma unroll 4
    for (int f = 0; f < DH; ++f) {
        u64 ad = dup2f(Os[t * OSTR + f]);
        const u64* wr = (const u64*)(Ws + f * DH);
        #pragma unroll
        for (int op = 0; op < 32; ++op) fma2(acc[op], ad, wr[op]);
    }
    const u64 iv = dup2f(inv);
    float* ob = out + b * DH * NSEQ + row0 + t;
    #pragma unroll
    for (int op = 0; op < 32; ++op) {
        float lo, hi;
        unpack2f(mul2(acc[op], iv), lo, hi);
        ob[(2 * op + 0) * NSEQ] = lo;
        ob[(2 * op + 1) * NSEQ] = hi;
    }
}

extern "C" void kernel_launch(void* const* d_in, const int* in_sizes, int n_in,
                              void* d_out, int out_size) {
    const float* x = (const float*)d_in[0];   // [4, 64, 8192] f32
    const float* w = (const float*)d_in[1];   // [64, 64] f32
    float* out = (float*)d_out;               // [4, 64, 8192] f32

    prep_kernel<<<dim3(NSEQ / 256, 4), 256>>>(x);

    cudaFuncSetAttribute(fa_h16_kernel, cudaFuncAttributeMaxDynamicSharedMemorySize,
                         SMEM_MAIN);
    fa_h16_kernel<<<dim3(NSEQ / BR, 4, 2), NT, SMEM_MAIN>>>();

    cudaFuncSetAttribute(combine_kernel, cudaFuncAttributeMaxDynamicSharedMemorySize,
                         SMEM_COMB);
    combine_kernel<<<dim3(NSEQ / BR, 4), NT, SMEM_COMB>>>(w, out);
}